// round 2
// baseline (speedup 1.0000x reference)
#include <cuda_runtime.h>
#include <math.h>

#define NB 64
#define NT 128
#define NN 64     // nodes
#define NC 128    // channels
#define NH 64     // hidden
#define NE 192    // 3 gates * 64
#define TP 68     // padded pitch for transposed 64x64 tiles

// Precomputed input-path gate contributions U[b,t,n,e] (biases included). 384 MiB.
static __device__ float g_U[(size_t)NB * NT * NN * NE];

// outT[d][n] = sum_m PT[d][m] * AT[m][n]   (i.e. out = A @ P, all transposed, pitch TP)
__device__ __forceinline__ void mmT64(float* __restrict__ outT,
                                      const float* __restrict__ PT,
                                      const float* __restrict__ AT,
                                      int tid)
{
    const int n0 = (tid & 15) * 4;
    const int d0 = (tid >> 4) * 4;
    float acc[4][4];
#pragma unroll
    for (int i = 0; i < 4; i++)
#pragma unroll
        for (int j = 0; j < 4; j++) acc[i][j] = 0.f;

#pragma unroll 4
    for (int m = 0; m < 64; m++) {
        float4 a4 = *(const float4*)&AT[m * TP + n0];
        float av[4] = {a4.x, a4.y, a4.z, a4.w};
        float p[4];
#pragma unroll
        for (int i = 0; i < 4; i++) p[i] = PT[(d0 + i) * TP + m];
#pragma unroll
        for (int i = 0; i < 4; i++)
#pragma unroll
            for (int j = 0; j < 4; j++) acc[i][j] += p[i] * av[j];
    }
#pragma unroll
    for (int i = 0; i < 4; i++)
        *(float4*)&outT[(d0 + i) * TP + n0] =
            make_float4(acc[i][0], acc[i][1], acc[i][2], acc[i][3]);
}

// ---------------------------------------------------------------------------
// Phase 1: per (b,t) tile. grid = 8192, block = 256.
// ---------------------------------------------------------------------------
__global__ void __launch_bounds__(256, 1) phase1_kernel(
    const float* __restrict__ frames, const float* __restrict__ adj,
    const float* __restrict__ encW, const float* __restrict__ encB,
    const float* __restrict__ Wfu, const float* __restrict__ Wgu, const float* __restrict__ Wcu,
    const float* __restrict__ bf, const float* __restrict__ bg, const float* __restrict__ bc)
{
    extern __shared__ float sm[];
    float* sStage = sm;                 // 16384: [sFr 8192 | sEW 8192], later sWu 12288
    float* sAT = sm + 16384;            // 4352
    float* sXT = sAT + 4352;            // 4352
    float* sYT = sXT + 4352;            // 4352
    float* sZT = sYT + 4352;            // 4352

    const int tid = threadIdx.x;
    const int bt = blockIdx.x;
    const float* fr = frames + (size_t)bt * (NC * NN);
    const float* Ap = adj + (size_t)bt * (NN * NN);

    // AT[m][n] = A[n][m]
    for (int i = tid; i < NN * NN; i += 256)
        sAT[(i & 63) * TP + (i >> 6)] = Ap[i];
    float* sFr = sStage;        // [c][n]  (frames natural layout)
    float* sEW = sStage + 8192; // [c][d]
    for (int i = tid; i < (NC * NN) / 4; i += 256)
        ((float4*)sFr)[i] = ((const float4*)fr)[i];
    for (int i = tid; i < (NC * NH) / 4; i += 256)
        ((float4*)sEW)[i] = ((const float4*)encW)[i];
    __syncthreads();

    const int n0 = (tid & 15) * 4;
    const int d0 = (tid >> 4) * 4;

    // Encode: xT[d][n] = sum_c encW[c][d] * fr[c][n] + encB[d]
    {
        float acc[4][4];
#pragma unroll
        for (int i = 0; i < 4; i++)
#pragma unroll
            for (int j = 0; j < 4; j++) acc[i][j] = 0.f;
#pragma unroll 4
        for (int c = 0; c < NC; c++) {
            float4 a4 = *(const float4*)&sFr[c * 64 + n0];
            float4 w4 = *(const float4*)&sEW[c * 64 + d0];
            float av[4] = {a4.x, a4.y, a4.z, a4.w};
            float wv[4] = {w4.x, w4.y, w4.z, w4.w};
#pragma unroll
            for (int i = 0; i < 4; i++)
#pragma unroll
                for (int j = 0; j < 4; j++) acc[i][j] += wv[i] * av[j];
        }
        float4 b4 = *(const float4*)&encB[d0];
        float bv[4] = {b4.x, b4.y, b4.z, b4.w};
#pragma unroll
        for (int i = 0; i < 4; i++)
            *(float4*)&sXT[(d0 + i) * TP + n0] =
                make_float4(acc[i][0] + bv[i], acc[i][1] + bv[i],
                            acc[i][2] + bv[i], acc[i][3] + bv[i]);
    }
    __syncthreads();
    mmT64(sYT, sXT, sAT, tid);   // y1 = A x
    __syncthreads();
    mmT64(sZT, sYT, sAT, tid);   // y2 = A y1
    __syncthreads();

    // U = sum_k y_k @ Wu_k  (+ biases), 3 gates fused
    float accf[4][4], accg[4][4], accc[4][4];
    {
        float4 vf = *(const float4*)&bf[d0];
        float4 vg = *(const float4*)&bg[d0];
        float4 vc = *(const float4*)&bc[d0];
        float fv[4] = {vf.x, vf.y, vf.z, vf.w};
        float gv[4] = {vg.x, vg.y, vg.z, vg.w};
        float cv[4] = {vc.x, vc.y, vc.z, vc.w};
#pragma unroll
        for (int i = 0; i < 4; i++)
#pragma unroll
            for (int j = 0; j < 4; j++) {
                accf[i][j] = fv[i]; accg[i][j] = gv[i]; accc[i][j] = cv[i];
            }
    }
    float* sWu = sStage;  // 64 x 192
#pragma unroll 1
    for (int k = 0; k < 3; k++) {
        __syncthreads();
        for (int i = tid; i < 4096; i += 256) {
            int dd = i >> 6, e = i & 63;
            sWu[dd * NE + e]       = Wfu[k * 4096 + i];
            sWu[dd * NE + 64 + e]  = Wgu[k * 4096 + i];
            sWu[dd * NE + 128 + e] = Wcu[k * 4096 + i];
        }
        __syncthreads();
        const float* src = (k == 0) ? sXT : ((k == 1) ? sYT : sZT);
#pragma unroll 2
        for (int m = 0; m < 64; m++) {
            float4 x4 = *(const float4*)&src[m * TP + n0];
            float xv[4] = {x4.x, x4.y, x4.z, x4.w};
            float4 wf4 = *(const float4*)&sWu[m * NE + d0];
            float4 wg4 = *(const float4*)&sWu[m * NE + 64 + d0];
            float4 wc4 = *(const float4*)&sWu[m * NE + 128 + d0];
            float wf[4] = {wf4.x, wf4.y, wf4.z, wf4.w};
            float wg[4] = {wg4.x, wg4.y, wg4.z, wg4.w};
            float wc[4] = {wc4.x, wc4.y, wc4.z, wc4.w};
#pragma unroll
            for (int i = 0; i < 4; i++)
#pragma unroll
                for (int j = 0; j < 4; j++) {
                    accf[i][j] += wf[i] * xv[j];
                    accg[i][j] += wg[i] * xv[j];
                    accc[i][j] += wc[i] * xv[j];
                }
        }
    }
    float* Ub = g_U + (size_t)bt * (NN * NE);
#pragma unroll
    for (int j = 0; j < 4; j++) {
        int row = (n0 + j) * NE;
        *(float4*)&Ub[row + d0]       = make_float4(accf[0][j], accf[1][j], accf[2][j], accf[3][j]);
        *(float4*)&Ub[row + 64 + d0]  = make_float4(accg[0][j], accg[1][j], accg[2][j], accg[3][j]);
        *(float4*)&Ub[row + 128 + d0] = make_float4(accc[0][j], accc[1][j], accc[2][j], accc[3][j]);
    }
}

// ---------------------------------------------------------------------------
// Phase 2: persistent recurrence. grid = 64, block = 256.
// ---------------------------------------------------------------------------
__global__ void __launch_bounds__(256, 1) phase2_kernel(
    const float* __restrict__ adj, const float* __restrict__ h0,
    const float* __restrict__ Wfh, const float* __restrict__ Wgh, const float* __restrict__ Wch,
    const float* __restrict__ dW1, const float* __restrict__ db1,
    const float* __restrict__ dW2, const float* __restrict__ db2,
    const float* __restrict__ dW3, const float* __restrict__ db3,
    const float* __restrict__ osc, const float* __restrict__ obi,
    float* __restrict__ out)
{
    extern __shared__ float sm[];
    float* sWh   = sm;                 // 3*64*192 = 36864
    float* sAT   = sm + 36864;         // 4352
    float* sHT   = sAT + 4352;         // 4352
    float* sH1T  = sHT + 4352;         // 4352
    float* sH2T  = sH1T + 4352;        // 4352
    float* sPool = sH2T + 4352;        // 64
    float* sZ1   = sPool + 64;         // 128
    float* sZ2   = sZ1 + 128;          // 64

    const int tid = threadIdx.x;
    const int b = blockIdx.x;

    // Stage hidden-path weights once: sWh[(k*64+m)*192 + {0,64,128}+e]
    for (int i = tid; i < 3 * 4096; i += 256) {
        int k = i >> 12; int r = i & 4095; int m = r >> 6; int e = r & 63;
        sWh[(k * 64 + m) * NE + e]       = Wfh[i];
        sWh[(k * 64 + m) * NE + 64 + e]  = Wgh[i];
        sWh[(k * 64 + m) * NE + 128 + e] = Wch[i];
    }
    // h0 transposed: sHT[d][n] = h0[b][n][d]
    for (int i = tid; i < 4096; i += 256)
        sHT[(i & 63) * TP + (i >> 6)] = h0[b * 4096 + i];
    __syncthreads();

    const int n0 = (tid & 15) * 4;
    const int d0 = (tid >> 4) * 4;

    for (int t = 0; t < NT; t++) {
        const float* Ap = adj + ((size_t)(b * NT + t)) * 4096;
        for (int i = tid; i < 4096; i += 256)
            sAT[(i & 63) * TP + (i >> 6)] = Ap[i];
        __syncthreads();
        mmT64(sH1T, sHT, sAT, tid);    // h1 = A h
        __syncthreads();
        mmT64(sH2T, sH1T, sAT, tid);   // h2 = A h1
        __syncthreads();

        // Gate pre-activations: G = U + sum_k h_k @ Wh_k
        const float* Ub = g_U + ((size_t)(b * NT + t)) * (NN * NE);
        float accf[4][4], accg[4][4], accc[4][4];
#pragma unroll
        for (int j = 0; j < 4; j++) {
            int row = (n0 + j) * NE;
            float4 uf = *(const float4*)&Ub[row + d0];
            float4 ug = *(const float4*)&Ub[row + 64 + d0];
            float4 uc = *(const float4*)&Ub[row + 128 + d0];
            accf[0][j] = uf.x; accf[1][j] = uf.y; accf[2][j] = uf.z; accf[3][j] = uf.w;
            accg[0][j] = ug.x; accg[1][j] = ug.y; accg[2][j] = ug.z; accg[3][j] = ug.w;
            accc[0][j] = uc.x; accc[1][j] = uc.y; accc[2][j] = uc.z; accc[3][j] = uc.w;
        }
#pragma unroll 1
        for (int k = 0; k < 3; k++) {
            const float* src = (k == 0) ? sHT : ((k == 1) ? sH1T : sH2T);
            const float* wb = sWh + k * 64 * NE;
#pragma unroll 2
            for (int m = 0; m < 64; m++) {
                float4 x4 = *(const float4*)&src[m * TP + n0];
                float xv[4] = {x4.x, x4.y, x4.z, x4.w};
                float4 wf4 = *(const float4*)&wb[m * NE + d0];
                float4 wg4 = *(const float4*)&wb[m * NE + 64 + d0];
                float4 wc4 = *(const float4*)&wb[m * NE + 128 + d0];
                float wf[4] = {wf4.x, wf4.y, wf4.z, wf4.w};
                float wg[4] = {wg4.x, wg4.y, wg4.z, wg4.w};
                float wc[4] = {wc4.x, wc4.y, wc4.z, wc4.w};
#pragma unroll
                for (int i = 0; i < 4; i++)
#pragma unroll
                    for (int j = 0; j < 4; j++) {
                        accf[i][j] += wf[i] * xv[j];
                        accg[i][j] += wg[i] * xv[j];
                        accc[i][j] += wc[i] * xv[j];
                    }
            }
        }
        __syncthreads();   // all reads of sHT done before overwrite

        // Nonlinearity + h update (registers -> sHT)
#pragma unroll
        for (int i = 0; i < 4; i++) {
            float hv[4];
#pragma unroll
            for (int j = 0; j < 4; j++) {
                float f = 1.0f / (1.0f + __expf(-accf[i][j]));
                hv[j] = f * tanhf(accg[i][j]) + (1.0f - f) * tanhf(accc[i][j]);
            }
            *(float4*)&sHT[(d0 + i) * TP + n0] = make_float4(hv[0], hv[1], hv[2], hv[3]);
        }
        __syncthreads();

        // Decoder MLP
        if (tid < 64) {
            float s = 0.f;
            for (int n = 0; n < 64; n++) s += sHT[tid * TP + n];
            sPool[tid] = s * (1.0f / 64.0f);
        }
        __syncthreads();
        if (tid < 128) {
            float a = db1[tid];
            for (int d = 0; d < 64; d++) a += sPool[d] * dW1[d * 128 + tid];
            sZ1[tid] = fmaxf(a, 0.f);
        }
        __syncthreads();
        if (tid < 64) {
            float a = db2[tid];
            for (int i = 0; i < 128; i++) a += sZ1[i] * dW2[i * 64 + tid];
            sZ2[tid] = fmaxf(a, 0.f);
        }
        __syncthreads();
        if (tid < 6) {
            float a = db3[tid];
            for (int j = 0; j < 64; j++) a += sZ2[j] * dW3[j * 6 + tid];
            out[((size_t)(b * NT + t)) * 6 + tid] = a * osc[tid] + obi[tid];
        }
        __syncthreads();
    }

    // final_hidden[b,0,n,d] = sHT[d][n], at out offset NB*NT*6
    float* fh = out + (size_t)NB * NT * 6 + (size_t)b * (NN * NH);
    for (int i = tid; i < 4096; i += 256)
        fh[i] = sHT[(i & 63) * TP + (i >> 6)];
}

extern "C" void kernel_launch(void* const* d_in, const int* in_sizes, int n_in,
                              void* d_out, int out_size) {
    const float* frames = (const float*)d_in[0];
    const float* adj    = (const float*)d_in[1];
    const float* h0     = (const float*)d_in[2];
    const float* encW   = (const float*)d_in[3];
    const float* encB   = (const float*)d_in[4];
    const float* Wfh    = (const float*)d_in[5];
    const float* Wfu    = (const float*)d_in[6];
    const float* bf     = (const float*)d_in[7];
    const float* Wgh    = (const float*)d_in[8];
    const float* Wgu    = (const float*)d_in[9];
    const float* bg     = (const float*)d_in[10];
    const float* Wch    = (const float*)d_in[11];
    const float* Wcu    = (const float*)d_in[12];
    const float* bc     = (const float*)d_in[13];
    const float* dW1    = (const float*)d_in[14];
    const float* db1    = (const float*)d_in[15];
    const float* dW2    = (const float*)d_in[16];
    const float* db2    = (const float*)d_in[17];
    const float* dW3    = (const float*)d_in[18];
    const float* db3    = (const float*)d_in[19];
    const float* osc    = (const float*)d_in[20];
    const float* obi    = (const float*)d_in[21];
    float* out = (float*)d_out;

    const int smem1 = 38144 * 4;   // 152576 B
    const int smem2 = 54528 * 4;   // 218112 B
    cudaFuncSetAttribute(phase1_kernel, cudaFuncAttributeMaxDynamicSharedMemorySize, smem1);
    cudaFuncSetAttribute(phase2_kernel, cudaFuncAttributeMaxDynamicSharedMemorySize, smem2);

    phase1_kernel<<<NB * NT, 256, smem1>>>(frames, adj, encW, encB,
                                           Wfu, Wgu, Wcu, bf, bg, bc);
    phase2_kernel<<<NB, 256, smem2>>>(adj, h0, Wfh, Wgh, Wch,
                                      dW1, db1, dW2, db2, dW3, db3,
                                      osc, obi, out);
}